// round 3
// baseline (speedup 1.0000x reference)
#include <cuda_runtime.h>

#define BB 256
#define TT 4096
#define DD 3
#define KK 2
#define HH 2
#define AA 5
#define EHD 8

// ---- scratch (static device globals; no allocations) ----
__device__ __align__(16) float g_gi[(size_t)TT * BB * 8];     // [T,B,8] (6 used)
__device__ __align__(16) float g_e[(size_t)TT * BB * 2];      // [T,B,2]
__device__ __align__(16) float g_h[(size_t)BB * TT * 2];      // [B,T,2]
__device__ __align__(16) float g_alpha[(size_t)BB * TT * 2];  // [B,T,2]
__device__ __align__(16) float g_beta[(size_t)BB * TT * 2];   // [B,T,2]

__device__ __forceinline__ float tanh_apx(float x) {
    float y;
    asm("tanh.approx.f32 %0, %1;" : "=f"(y) : "f"(x));
    return y;
}

__device__ __forceinline__ float lse2(float x, float y) {
    float m = fmaxf(x, y);
    float d = fminf(x, y) - m;
    return m + __logf(1.0f + __expf(d));
}

// ============================================================
// Kernel A: per-(b,t) parallel precompute of emitter e and GRU input gates gi
// ============================================================
__global__ void prep_kernel(const float* __restrict__ x,
                            const float* __restrict__ fc1_w, const float* __restrict__ fc1_b,
                            const float* __restrict__ fc2_w, const float* __restrict__ fc2_b,
                            const float* __restrict__ w_ih, const float* __restrict__ b_ih) {
    int id = blockIdx.x * blockDim.x + threadIdx.x;
    if (id >= BB * TT) return;
    int b = id & (BB - 1);
    int t = id >> 8;  // id / BB

    const float* xp = x + ((size_t)b * TT + t) * 3;
    float x0 = xp[0], x1 = xp[1], x2 = xp[2];

    // emitter: e = log_softmax(tanh(x@fc1^T+b1) @ fc2^T + b2)
    float l0 = fc2_b[0], l1 = fc2_b[1];
#pragma unroll
    for (int e = 0; e < EHD; e++) {
        float q = tanhf(fc1_w[e * 3 + 0] * x0 + fc1_w[e * 3 + 1] * x1 +
                        fc1_w[e * 3 + 2] * x2 + fc1_b[e]);
        l0 += fc2_w[e] * q;
        l1 += fc2_w[EHD + e] * q;
    }
    float m = fmaxf(l0, l1);
    float ls = m + __logf(__expf(l0 - m) + __expf(l1 - m));
    float2* ep = (float2*)g_e;
    ep[(size_t)t * BB + b] = make_float2(l0 - ls, l1 - ls);

    // GRU input projection: gi[j] = w_ih[j]·x + b_ih[j]  (j = r0,r1,z0,z1,n0,n1)
    float gv[6];
#pragma unroll
    for (int j = 0; j < 6; j++)
        gv[j] = w_ih[j * 3 + 0] * x0 + w_ih[j * 3 + 1] * x1 + w_ih[j * 3 + 2] * x2 + b_ih[j];
    float4* gp = (float4*)g_gi;
    size_t off = ((size_t)t * BB + b) * 2;
    gp[off + 0] = make_float4(gv[0], gv[1], gv[2], gv[3]);
    gp[off + 1] = make_float4(gv[4], gv[5], 0.f, 0.f);
}

// ============================================================
// Kernel B: three concurrent sequential scans (GRU, HMM fwd, HMM bwd)
// grid = 24 blocks x 32 threads: blocks 0-7 GRU, 8-15 fwd(alpha), 16-23 bwd(beta)
// ============================================================
__global__ void scan_kernel(const float* __restrict__ w_hh, const float* __restrict__ b_hh,
                            const float* __restrict__ log_pi, const float* __restrict__ log_A) {
    int role = blockIdx.x >> 3;
    int b = ((blockIdx.x & 7) << 5) + threadIdx.x;  // 0..255

    if (role == 0) {
        // ---------------- GRU ----------------
        float whh[6][2], bhh[6];
#pragma unroll
        for (int j = 0; j < 6; j++) {
            whh[j][0] = w_hh[j * 2];
            whh[j][1] = w_hh[j * 2 + 1];
            bhh[j] = b_hh[j];
        }
        float h0 = 0.f, h1 = 0.f;
        const float4* gp = (const float4*)g_gi;
        float2* hout = (float2*)g_h;

        float4 bufA[4], bufB[4];
#pragma unroll
        for (int i = 0; i < 4; i++) {
            size_t off = ((size_t)i * BB + b) * 2;
            bufA[i] = gp[off];
            bufB[i] = gp[off + 1];
        }
        for (int t0 = 0; t0 < TT; t0 += 4) {
#pragma unroll
            for (int i = 0; i < 4; i++) {
                int t = t0 + i;
                float4 A = bufA[i];
                float4 Bv = bufB[i];
                int tn = t + 4;
                if (tn >= TT) tn = TT - 1;
                size_t off = ((size_t)tn * BB + b) * 2;
                bufA[i] = gp[off];
                bufB[i] = gp[off + 1];

                float hr0 = whh[0][0] * h0 + whh[0][1] * h1 + bhh[0];
                float hr1 = whh[1][0] * h0 + whh[1][1] * h1 + bhh[1];
                float hz0 = whh[2][0] * h0 + whh[2][1] * h1 + bhh[2];
                float hz1 = whh[3][0] * h0 + whh[3][1] * h1 + bhh[3];
                float hn0 = whh[4][0] * h0 + whh[4][1] * h1 + bhh[4];
                float hn1 = whh[5][0] * h0 + whh[5][1] * h1 + bhh[5];
                // sigmoid(x) = 0.5*tanh(0.5x)+0.5
                float r0 = fmaf(0.5f, tanh_apx(0.5f * (A.x + hr0)), 0.5f);
                float r1 = fmaf(0.5f, tanh_apx(0.5f * (A.y + hr1)), 0.5f);
                float z0 = fmaf(0.5f, tanh_apx(0.5f * (A.z + hz0)), 0.5f);
                float z1 = fmaf(0.5f, tanh_apx(0.5f * (A.w + hz1)), 0.5f);
                float n0 = tanh_apx(fmaf(r0, hn0, Bv.x));
                float n1 = tanh_apx(fmaf(r1, hn1, Bv.y));
                h0 = fmaf(z0, h0 - n0, n0);
                h1 = fmaf(z1, h1 - n1, n1);
                hout[(size_t)b * TT + t] = make_float2(h0, h1);
            }
        }
    } else {
        // shared param prep for HMM roles
        float lA00, lA01, lA10, lA11, lpi0, lpi1;
        {
            float a0 = log_A[0], a1 = log_A[1], a2 = log_A[2], a3 = log_A[3];
            float m0 = fmaxf(a0, a1);
            float s0 = m0 + logf(expf(a0 - m0) + expf(a1 - m0));
            float m1 = fmaxf(a2, a3);
            float s1 = m1 + logf(expf(a2 - m1) + expf(a3 - m1));
            lA00 = a0 - s0; lA01 = a1 - s0; lA10 = a2 - s1; lA11 = a3 - s1;
            float p0 = log_pi[0], p1 = log_pi[1];
            float mp = fmaxf(p0, p1);
            float sp = mp + logf(expf(p0 - mp) + expf(p1 - mp));
            lpi0 = p0 - sp; lpi1 = p1 - sp;
        }
        const float2* ep = (const float2*)g_e;

        if (role == 1) {
            // ---------------- HMM forward (alpha) ----------------
            float2* ap = (float2*)g_alpha;
            float2 e0v = ep[b];
            float a0 = lpi0 + e0v.x, a1 = lpi1 + e0v.y;
            ap[(size_t)b * TT] = make_float2(a0, a1);

            float2 buf[4];
#pragma unroll
            for (int i = 0; i < 4; i++) {
                int t = 1 + i;
                if (t >= TT) t = TT - 1;
                buf[i] = ep[(size_t)t * BB + b];
            }
            for (int t0 = 1; t0 < TT; t0 += 4) {
#pragma unroll
                for (int i = 0; i < 4; i++) {
                    int t = t0 + i;
                    if (t >= TT) break;
                    float2 ev = buf[i];
                    int tn = t + 4;
                    if (tn >= TT) tn = TT - 1;
                    buf[i] = ep[(size_t)tn * BB + b];
                    float n0 = lse2(a0 + lA00, a1 + lA10) + ev.x;
                    float n1 = lse2(a0 + lA01, a1 + lA11) + ev.y;
                    a0 = n0; a1 = n1;
                    ap[(size_t)b * TT + t] = make_float2(a0, a1);
                }
            }
        } else {
            // ---------------- HMM backward (beta) ----------------
            float2* bp = (float2*)g_beta;
            float b0 = 0.f, b1 = 0.f;
            bp[(size_t)b * TT + (TT - 1)] = make_float2(0.f, 0.f);

            float2 buf[4];
#pragma unroll
            for (int i = 0; i < 4; i++) {
                int te = (TT - 1) - i;  // e index for step t = T-2-i
                buf[i] = ep[(size_t)te * BB + b];
            }
            for (int t0 = TT - 2; t0 >= 0; t0 -= 4) {
#pragma unroll
                for (int i = 0; i < 4; i++) {
                    int t = t0 - i;
                    if (t < 0) break;
                    float2 ev = buf[i];  // e[t+1]
                    int tn = t - 3;      // (t+1) - 4, for step t-4 (same slot)
                    if (tn < 0) tn = 0;
                    buf[i] = ep[(size_t)tn * BB + b];
                    float c0 = b0 + ev.x, c1 = b1 + ev.y;
                    float nb0 = lse2(c0 + lA00, c1 + lA01);
                    float nb1 = lse2(c0 + lA10, c1 + lA11);
                    b0 = nb0; b1 = nb1;
                    bp[(size_t)b * TT + t] = make_float2(b0, b1);
                }
            }
        }
    }
}

// ============================================================
// Kernel C: per-(b,t) parallel posterior + mixture gating + outputs
// out = [ pi_log (B,T,2) | g (B,T,5) | log_gamma (B,T,2) ] flattened
// ============================================================
__global__ void gate_kernel(const float* __restrict__ Q_seq, const float* __restrict__ Wg,
                            const float* __restrict__ by, float* __restrict__ out) {
    int id = blockIdx.x * blockDim.x + threadIdx.x;  // id = b*T + t (t inner)
    if (id >= BB * TT) return;

    const float2* ap = (const float2*)g_alpha;
    const float2* bp = (const float2*)g_beta;
    const float2* hp = (const float2*)g_h;
    float2 av = ap[id], bv = bp[id], hv = hp[id];

    float lg0 = av.x + bv.x, lg1 = av.y + bv.y;
    float m = fmaxf(lg0, lg1);
    float ls = m + __logf(__expf(lg0 - m) + __expf(lg1 - m));
    lg0 -= ls; lg1 -= ls;
    float gam0 = __expf(lg0), gam1 = __expf(lg1);

    // Wh[k][a] = h0*Wg[k][0][a] + h1*Wg[k][1][a]; softmax over a
    float wa[5], wb[5];
#pragma unroll
    for (int a = 0; a < 5; a++) {
        wa[a] = hv.x * Wg[a] + hv.y * Wg[5 + a];
        wb[a] = hv.x * Wg[10 + a] + hv.y * Wg[15 + a];
    }
    float ma = wa[0], mb = wb[0];
#pragma unroll
    for (int a = 1; a < 5; a++) {
        ma = fmaxf(ma, wa[a]);
        mb = fmaxf(mb, wb[a]);
    }
    float sa = 0.f, sb = 0.f;
#pragma unroll
    for (int a = 0; a < 5; a++) {
        wa[a] = __expf(wa[a] - ma); sa += wa[a];
        wb[a] = __expf(wb[a] - mb); sb += wb[a];
    }
    float ra = gam0 / sa, rb = gam1 / sb;

    const float* qp = Q_seq + (size_t)id * 10;
    float V0 = gam0 * by[0] + gam1 * by[2];
    float V1 = gam0 * by[1] + gam1 * by[3];
    float g[5];
#pragma unroll
    for (int a = 0; a < 5; a++) {
        float ga = wa[a] * ra + wb[a] * rb;
        g[a] = ga;
        V0 += ga * qp[a * 2 + 0];
        V1 += ga * qp[a * 2 + 1];
    }
    float mv = fmaxf(V0, V1);
    float lsv = mv + __logf(__expf(V0 - mv) + __expf(V1 - mv));

    float* out_pi = out + (size_t)id * 2;
    out_pi[0] = V0 - lsv;
    out_pi[1] = V1 - lsv;
    float* out_g = out + (size_t)BB * TT * 2 + (size_t)id * 5;
#pragma unroll
    for (int a = 0; a < 5; a++) out_g[a] = g[a];
    float* out_lg = out + (size_t)BB * TT * 7 + (size_t)id * 2;
    out_lg[0] = lg0;
    out_lg[1] = lg1;
}

extern "C" void kernel_launch(void* const* d_in, const int* in_sizes, int n_in,
                              void* d_out, int out_size) {
    const float* x      = (const float*)d_in[0];
    const float* Q_seq  = (const float*)d_in[1];
    const float* log_pi = (const float*)d_in[2];
    const float* log_A  = (const float*)d_in[3];
    const float* fc1_w  = (const float*)d_in[4];
    const float* fc1_b  = (const float*)d_in[5];
    const float* fc2_w  = (const float*)d_in[6];
    const float* fc2_b  = (const float*)d_in[7];
    const float* w_ih   = (const float*)d_in[8];
    const float* w_hh   = (const float*)d_in[9];
    const float* b_ih   = (const float*)d_in[10];
    const float* b_hh   = (const float*)d_in[11];
    const float* Wg     = (const float*)d_in[12];
    const float* by     = (const float*)d_in[13];
    float* out = (float*)d_out;

    int n = BB * TT;
    prep_kernel<<<(n + 255) / 256, 256>>>(x, fc1_w, fc1_b, fc2_w, fc2_b, w_ih, b_ih);
    scan_kernel<<<24, 32>>>(w_hh, b_hh, log_pi, log_A);
    gate_kernel<<<(n + 255) / 256, 256>>>(Q_seq, Wg, by, out);
}

// round 4
// speedup vs baseline: 12.3008x; 12.3008x over previous
#include <cuda_runtime.h>

#define BB 256
#define TT 4096
#define EHD 8

#define GRU_L 128
#define GRU_W 96
#define HMM_L 128
#define HMM_W 32
#define NCHUNK 32   // TT / 128

// ---- scratch (static device globals; no allocations) ----
// all [T,B] layouts (coalesced for lane = b)
__device__ __align__(16) float4 g_xT[(size_t)TT * BB];     // x transposed, .w unused
__device__ __align__(16) float2 g_e[(size_t)TT * BB];      // emitter log-probs
__device__ __align__(16) float2 g_h[(size_t)TT * BB];      // GRU hidden
__device__ __align__(16) float2 g_alpha[(size_t)TT * BB];
__device__ __align__(16) float2 g_beta[(size_t)TT * BB];

__device__ __forceinline__ float tanh_apx(float x) {
    float y;
    asm("tanh.approx.f32 %0, %1;" : "=f"(y) : "f"(x));
    return y;
}

__device__ __forceinline__ float lse2(float x, float y) {
    float m = fmaxf(x, y);
    float d = fminf(x, y) - m;
    return m + __logf(1.0f + __expf(d));
}

// ============================================================
// Kernel A: tiled transpose of x + emitter e.  32b x 32t tiles.
// grid (B/32, T/32), 256 threads.
// ============================================================
__global__ void prep_kernel(const float* __restrict__ x,
                            const float* __restrict__ fc1_w, const float* __restrict__ fc1_b,
                            const float* __restrict__ fc2_w, const float* __restrict__ fc2_b) {
    __shared__ float smx[32][97];  // 32 rows (b) x 96 floats (32 t x 3) + pad
    int tid = threadIdx.x;
    int b0 = blockIdx.x << 5;
    int t0 = blockIdx.y << 5;
    int lane = tid & 31;
    int w = tid >> 5;

    // load: each warp handles 4 b-rows, 3 coalesced 128B reads per row
#pragma unroll
    for (int i = 0; i < 4; i++) {
        int bl = w * 4 + i;
        const float* src = x + ((size_t)(b0 + bl) * TT + t0) * 3;
#pragma unroll
        for (int j = 0; j < 3; j++)
            smx[bl][j * 32 + lane] = src[j * 32 + lane];
    }
    __syncthreads();

    // compute phase: lane = b (coalesced writes), 4 passes over t
#pragma unroll
    for (int r = 0; r < 4; r++) {
        int t_l = (tid >> 5) + r * 8;
        int b_l = tid & 31;
        float x0 = smx[b_l][t_l * 3 + 0];
        float x1 = smx[b_l][t_l * 3 + 1];
        float x2 = smx[b_l][t_l * 3 + 2];

        // emitter: log_softmax(tanh(x@fc1^T+b1) @ fc2^T + b2)
        float l0 = fc2_b[0], l1 = fc2_b[1];
#pragma unroll
        for (int e = 0; e < EHD; e++) {
            float q = tanhf(fmaf(fc1_w[e * 3 + 0], x0,
                            fmaf(fc1_w[e * 3 + 1], x1,
                            fmaf(fc1_w[e * 3 + 2], x2, fc1_b[e]))));
            l0 = fmaf(fc2_w[e], q, l0);
            l1 = fmaf(fc2_w[EHD + e], q, l1);
        }
        float m = fmaxf(l0, l1);
        float ls = m + __logf(__expf(l0 - m) + __expf(l1 - m));

        size_t o = (size_t)(t0 + t_l) * BB + (b0 + b_l);
        g_e[o] = make_float2(l0 - ls, l1 - ls);
        g_xT[o] = make_float4(x0, x1, x2, 0.f);
    }
}

// ============================================================
// Kernel B: chunked scans with warm-up.
// 768 warps: [0,256) GRU, [256,512) HMM fwd, [512,768) HMM bwd.
// warp handles 32 consecutive b's for one 128-step chunk.
// blockDim 128 (4 warps), grid 192.
// ============================================================
__global__ void scan_kernel(const float* __restrict__ w_ih, const float* __restrict__ b_ih,
                            const float* __restrict__ w_hh, const float* __restrict__ b_hh,
                            const float* __restrict__ log_pi, const float* __restrict__ log_A) {
    int wg = blockIdx.x * 4 + (threadIdx.x >> 5);
    int role = wg >> 8;          // 0 GRU, 1 fwd, 2 bwd
    int idx = wg & 255;
    int b = ((idx & 7) << 5) + (threadIdx.x & 31);
    int c = idx >> 3;            // chunk 0..31
    int cL = c << 7;             // chunk start

    if (role == 0) {
        // ---------------- GRU chunk ----------------
        float wih[6][3], bih[6], whh[6][2], bhh[6];
#pragma unroll
        for (int j = 0; j < 6; j++) {
            wih[j][0] = w_ih[j * 3 + 0];
            wih[j][1] = w_ih[j * 3 + 1];
            wih[j][2] = w_ih[j * 3 + 2];
            bih[j] = b_ih[j];
            whh[j][0] = w_hh[j * 2];
            whh[j][1] = w_hh[j * 2 + 1];
            bhh[j] = b_hh[j];
        }
        int ts = cL - GRU_W; if (ts < 0) ts = 0;
        int te = cL + GRU_L;
        float h0 = 0.f, h1 = 0.f;

        float4 buf[4];
#pragma unroll
        for (int i = 0; i < 4; i++) {
            int t = ts + i; if (t > TT - 1) t = TT - 1;
            buf[i] = g_xT[(size_t)t * BB + b];
        }
#pragma unroll 4
        for (int t = ts; t < te; t++) {
            float4 xv = buf[t & 3];
            int tn = t + 4; if (tn > TT - 1) tn = TT - 1;
            buf[t & 3] = g_xT[(size_t)tn * BB + b];

            // input gates (off critical path)
            float gr0 = fmaf(wih[0][0], xv.x, fmaf(wih[0][1], xv.y, fmaf(wih[0][2], xv.z, bih[0])));
            float gr1 = fmaf(wih[1][0], xv.x, fmaf(wih[1][1], xv.y, fmaf(wih[1][2], xv.z, bih[1])));
            float gz0 = fmaf(wih[2][0], xv.x, fmaf(wih[2][1], xv.y, fmaf(wih[2][2], xv.z, bih[2])));
            float gz1 = fmaf(wih[3][0], xv.x, fmaf(wih[3][1], xv.y, fmaf(wih[3][2], xv.z, bih[3])));
            float gn0 = fmaf(wih[4][0], xv.x, fmaf(wih[4][1], xv.y, fmaf(wih[4][2], xv.z, bih[4])));
            float gn1 = fmaf(wih[5][0], xv.x, fmaf(wih[5][1], xv.y, fmaf(wih[5][2], xv.z, bih[5])));

            float hr0 = fmaf(whh[0][0], h0, fmaf(whh[0][1], h1, bhh[0]));
            float hr1 = fmaf(whh[1][0], h0, fmaf(whh[1][1], h1, bhh[1]));
            float hz0 = fmaf(whh[2][0], h0, fmaf(whh[2][1], h1, bhh[2]));
            float hz1 = fmaf(whh[3][0], h0, fmaf(whh[3][1], h1, bhh[3]));
            float hn0 = fmaf(whh[4][0], h0, fmaf(whh[4][1], h1, bhh[4]));
            float hn1 = fmaf(whh[5][0], h0, fmaf(whh[5][1], h1, bhh[5]));
            // sigmoid(x) = 0.5*tanh(0.5x)+0.5
            float r0 = fmaf(0.5f, tanh_apx(0.5f * (gr0 + hr0)), 0.5f);
            float r1 = fmaf(0.5f, tanh_apx(0.5f * (gr1 + hr1)), 0.5f);
            float z0 = fmaf(0.5f, tanh_apx(0.5f * (gz0 + hz0)), 0.5f);
            float z1 = fmaf(0.5f, tanh_apx(0.5f * (gz1 + hz1)), 0.5f);
            float n0 = tanh_apx(fmaf(r0, hn0, gn0));
            float n1 = tanh_apx(fmaf(r1, hn1, gn1));
            h0 = fmaf(z0, h0 - n0, n0);
            h1 = fmaf(z1, h1 - n1, n1);
            if (t >= cL) g_h[(size_t)t * BB + b] = make_float2(h0, h1);
        }
    } else {
        // normalized HMM params
        float lA00, lA01, lA10, lA11, lpi0, lpi1;
        {
            float a0 = log_A[0], a1 = log_A[1], a2 = log_A[2], a3 = log_A[3];
            float m0 = fmaxf(a0, a1);
            float s0 = m0 + logf(expf(a0 - m0) + expf(a1 - m0));
            float m1 = fmaxf(a2, a3);
            float s1 = m1 + logf(expf(a2 - m1) + expf(a3 - m1));
            lA00 = a0 - s0; lA01 = a1 - s0; lA10 = a2 - s1; lA11 = a3 - s1;
            float p0 = log_pi[0], p1 = log_pi[1];
            float mp = fmaxf(p0, p1);
            float sp = mp + logf(expf(p0 - mp) + expf(p1 - mp));
            lpi0 = p0 - sp; lpi1 = p1 - sp;
        }

        if (role == 1) {
            // ---------------- HMM forward chunk ----------------
            int ts = cL - HMM_W; if (ts < 0) ts = 0;
            int te = cL + HMM_L;
            float a0, a1;
            int tstart;
            if (ts == 0) {
                float2 e0 = g_e[b];
                a0 = lpi0 + e0.x; a1 = lpi1 + e0.y;
                if (cL == 0) g_alpha[b] = make_float2(a0, a1);
                tstart = 1;
            } else {
                float2 ei = g_e[(size_t)ts * BB + b];
                a0 = ei.x; a1 = ei.y;   // arbitrary init; forgotten by mixing
                tstart = ts + 1;
            }
            float2 buf[4];
#pragma unroll
            for (int i = 0; i < 4; i++) {
                int t = tstart + i; if (t > TT - 1) t = TT - 1;
                buf[t & 3] = g_e[(size_t)t * BB + b];
            }
#pragma unroll 4
            for (int t = tstart; t < te; t++) {
                float2 ev = buf[t & 3];
                int tn = t + 4; if (tn > TT - 1) tn = TT - 1;
                buf[t & 3] = g_e[(size_t)tn * BB + b];
                float n0 = lse2(a0 + lA00, a1 + lA10) + ev.x;
                float n1 = lse2(a0 + lA01, a1 + lA11) + ev.y;
                a0 = n0; a1 = n1;
                if (t >= cL) g_alpha[(size_t)t * BB + b] = make_float2(a0, a1);
            }
        } else {
            // ---------------- HMM backward chunk ----------------
            int tend = cL + HMM_L - 1;                 // last index this chunk owns
            int ti = tend + HMM_W; if (ti > TT - 1) ti = TT - 1;  // pseudo-start
            float b0v = 0.f, b1v = 0.f;
            if (ti == tend) g_beta[(size_t)ti * BB + b] = make_float2(0.f, 0.f);

            float2 buf[4];
#pragma unroll
            for (int i = 0; i < 4; i++) {
                int t = ti - 1 - i;                    // step t uses e[t+1]
                buf[t & 3] = g_e[(size_t)(t + 1) * BB + b];
            }
#pragma unroll 4
            for (int t = ti - 1; t >= cL; t--) {
                float2 ev = buf[t & 3];
                int ip = t - 3; if (ip < 0) ip = 0;
                buf[t & 3] = g_e[(size_t)ip * BB + b];
                float c0 = b0v + ev.x, c1 = b1v + ev.y;
                b0v = lse2(c0 + lA00, c1 + lA01);
                b1v = lse2(c0 + lA10, c1 + lA11);
                if (t <= tend) g_beta[(size_t)t * BB + b] = make_float2(b0v, b1v);
            }
        }
    }
}

// ============================================================
// Kernel C: tiled gate. Loads h/alpha/beta [T,B] tiles via smem
// transpose, reads Q / writes outputs coalesced along t.
// grid (B/32, T/32), 256 threads.
// ============================================================
__global__ void gate_kernel(const float* __restrict__ Q_seq, const float* __restrict__ Wg,
                            const float* __restrict__ by, float* __restrict__ out) {
    __shared__ float2 sa[32][33], sb[32][33], sh[32][33];
    int tid = threadIdx.x;
    int b0 = blockIdx.x << 5;
    int t0 = blockIdx.y << 5;

#pragma unroll
    for (int r = 0; r < 4; r++) {
        int t_l = (tid >> 5) + r * 8;
        int b_l = tid & 31;
        size_t o = (size_t)(t0 + t_l) * BB + (b0 + b_l);
        sa[t_l][b_l] = g_alpha[o];
        sb[t_l][b_l] = g_beta[o];
        sh[t_l][b_l] = g_h[o];
    }
    __syncthreads();

#pragma unroll
    for (int r = 0; r < 4; r++) {
        int b_l = (tid >> 5) + r * 8;
        int t_l = tid & 31;
        float2 av = sa[t_l][b_l];
        float2 bv = sb[t_l][b_l];
        float2 hv = sh[t_l][b_l];
        size_t id = (size_t)(b0 + b_l) * TT + (t0 + t_l);

        float lg0 = av.x + bv.x, lg1 = av.y + bv.y;
        float m = fmaxf(lg0, lg1);
        float ls = m + __logf(__expf(lg0 - m) + __expf(lg1 - m));
        lg0 -= ls; lg1 -= ls;
        float gam0 = __expf(lg0), gam1 = __expf(lg1);

        float wa[5], wb[5];
#pragma unroll
        for (int a = 0; a < 5; a++) {
            wa[a] = hv.x * Wg[a] + hv.y * Wg[5 + a];
            wb[a] = hv.x * Wg[10 + a] + hv.y * Wg[15 + a];
        }
        float ma = wa[0], mb = wb[0];
#pragma unroll
        for (int a = 1; a < 5; a++) {
            ma = fmaxf(ma, wa[a]);
            mb = fmaxf(mb, wb[a]);
        }
        float sa_ = 0.f, sb_ = 0.f;
#pragma unroll
        for (int a = 0; a < 5; a++) {
            wa[a] = __expf(wa[a] - ma); sa_ += wa[a];
            wb[a] = __expf(wb[a] - mb); sb_ += wb[a];
        }
        float ra = gam0 / sa_, rb = gam1 / sb_;

        const float* qp = Q_seq + id * 10;
        float V0 = gam0 * by[0] + gam1 * by[2];
        float V1 = gam0 * by[1] + gam1 * by[3];
        float g[5];
#pragma unroll
        for (int a = 0; a < 5; a++) {
            float ga = wa[a] * ra + wb[a] * rb;
            g[a] = ga;
            V0 = fmaf(ga, qp[a * 2 + 0], V0);
            V1 = fmaf(ga, qp[a * 2 + 1], V1);
        }
        float mv = fmaxf(V0, V1);
        float lsv = mv + __logf(__expf(V0 - mv) + __expf(V1 - mv));

        float* out_pi = out + id * 2;
        out_pi[0] = V0 - lsv;
        out_pi[1] = V1 - lsv;
        float* out_g = out + (size_t)BB * TT * 2 + id * 5;
#pragma unroll
        for (int a = 0; a < 5; a++) out_g[a] = g[a];
        float* out_lg = out + (size_t)BB * TT * 7 + id * 2;
        out_lg[0] = lg0;
        out_lg[1] = lg1;
    }
}

extern "C" void kernel_launch(void* const* d_in, const int* in_sizes, int n_in,
                              void* d_out, int out_size) {
    const float* x      = (const float*)d_in[0];
    const float* Q_seq  = (const float*)d_in[1];
    const float* log_pi = (const float*)d_in[2];
    const float* log_A  = (const float*)d_in[3];
    const float* fc1_w  = (const float*)d_in[4];
    const float* fc1_b  = (const float*)d_in[5];
    const float* fc2_w  = (const float*)d_in[6];
    const float* fc2_b  = (const float*)d_in[7];
    const float* w_ih   = (const float*)d_in[8];
    const float* w_hh   = (const float*)d_in[9];
    const float* b_ih   = (const float*)d_in[10];
    const float* b_hh   = (const float*)d_in[11];
    const float* Wg     = (const float*)d_in[12];
    const float* by     = (const float*)d_in[13];
    float* out = (float*)d_out;

    dim3 tiles(BB / 32, TT / 32);
    prep_kernel<<<tiles, 256>>>(x, fc1_w, fc1_b, fc2_w, fc2_b);
    scan_kernel<<<192, 128>>>(w_ih, b_ih, w_hh, b_hh, log_pi, log_A);
    gate_kernel<<<tiles, 256>>>(Q_seq, Wg, by, out);
}

// round 5
// speedup vs baseline: 16.9775x; 1.3802x over previous
#include <cuda_runtime.h>

#define BB 256
#define TT 4096
#define EHD 8

#define CH_L 64        // chunk length (all roles)
#define GRU_W 48       // GRU warm-up
#define HMM_W 16       // HMM warm-up
#define NCHUNK (TT / CH_L)   // 64

// ---- scratch (static device globals; no allocations) ----
// all [T,B] layouts (coalesced for lane = b)
__device__ __align__(16) float4 g_xT[(size_t)TT * BB];     // x transposed, .w unused
__device__ __align__(16) float2 g_e[(size_t)TT * BB];      // emitter log-probs
__device__ __align__(16) float2 g_h[(size_t)TT * BB];      // GRU hidden
__device__ __align__(16) float2 g_alpha[(size_t)TT * BB];
__device__ __align__(16) float2 g_beta[(size_t)TT * BB];

__device__ __forceinline__ float tanh_apx(float x) {
    float y;
    asm("tanh.approx.f32 %0, %1;" : "=f"(y) : "f"(x));
    return y;
}

__device__ __forceinline__ float lse2(float x, float y) {
    float m = fmaxf(x, y);
    float d = fminf(x, y) - m;
    return m + __logf(1.0f + __expf(d));
}

// ============================================================
// Kernel A: tiled transpose of x + emitter e.  32b x 32t tiles.
// grid (B/32, T/32), 256 threads.
// ============================================================
__global__ void prep_kernel(const float* __restrict__ x,
                            const float* __restrict__ fc1_w, const float* __restrict__ fc1_b,
                            const float* __restrict__ fc2_w, const float* __restrict__ fc2_b) {
    __shared__ float smx[32][97];  // 32 rows (b) x 96 floats (32 t x 3) + pad
    int tid = threadIdx.x;
    int b0 = blockIdx.x << 5;
    int t0 = blockIdx.y << 5;
    int lane = tid & 31;
    int w = tid >> 5;

    // load: each warp handles 4 b-rows, 3 coalesced 128B reads per row
#pragma unroll
    for (int i = 0; i < 4; i++) {
        int bl = w * 4 + i;
        const float* src = x + ((size_t)(b0 + bl) * TT + t0) * 3;
#pragma unroll
        for (int j = 0; j < 3; j++)
            smx[bl][j * 32 + lane] = src[j * 32 + lane];
    }
    __syncthreads();

    // compute phase: lane = b (coalesced writes), 4 passes over t
#pragma unroll
    for (int r = 0; r < 4; r++) {
        int t_l = (tid >> 5) + r * 8;
        int b_l = tid & 31;
        float x0 = smx[b_l][t_l * 3 + 0];
        float x1 = smx[b_l][t_l * 3 + 1];
        float x2 = smx[b_l][t_l * 3 + 2];

        // emitter: log_softmax(tanh(x@fc1^T+b1) @ fc2^T + b2)
        float l0 = fc2_b[0], l1 = fc2_b[1];
#pragma unroll
        for (int e = 0; e < EHD; e++) {
            float q = tanh_apx(fmaf(fc1_w[e * 3 + 0], x0,
                               fmaf(fc1_w[e * 3 + 1], x1,
                               fmaf(fc1_w[e * 3 + 2], x2, fc1_b[e]))));
            l0 = fmaf(fc2_w[e], q, l0);
            l1 = fmaf(fc2_w[EHD + e], q, l1);
        }
        float m = fmaxf(l0, l1);
        float ls = m + __logf(__expf(l0 - m) + __expf(l1 - m));

        size_t o = (size_t)(t0 + t_l) * BB + (b0 + b_l);
        g_e[o] = make_float2(l0 - ls, l1 - ls);
        g_xT[o] = make_float4(x0, x1, x2, 0.f);
    }
}

// ============================================================
// Kernel B: chunked scans with warm-up.
// 1536 warps: [0,512) GRU, [512,1024) HMM fwd, [1024,1536) HMM bwd.
// warp handles 32 consecutive b's for one 64-step chunk.
// blockDim 128 (4 warps), grid 384.
// ============================================================
__global__ void scan_kernel(const float* __restrict__ w_ih, const float* __restrict__ b_ih,
                            const float* __restrict__ w_hh, const float* __restrict__ b_hh,
                            const float* __restrict__ log_pi, const float* __restrict__ log_A) {
    int wg = blockIdx.x * 4 + (threadIdx.x >> 5);
    int role = wg >> 9;          // 0 GRU, 1 fwd, 2 bwd
    int idx = wg & 511;
    int b = ((idx & 7) << 5) + (threadIdx.x & 31);
    int c = idx >> 3;            // chunk 0..63
    int cL = c << 6;             // chunk start

    if (role == 0) {
        // ---------------- GRU chunk ----------------
        float wih[6][3], bih[6], whh[6][2], bhh[6];
#pragma unroll
        for (int j = 0; j < 6; j++) {
            wih[j][0] = w_ih[j * 3 + 0];
            wih[j][1] = w_ih[j * 3 + 1];
            wih[j][2] = w_ih[j * 3 + 2];
            bih[j] = b_ih[j];
            whh[j][0] = w_hh[j * 2];
            whh[j][1] = w_hh[j * 2 + 1];
            bhh[j] = b_hh[j];
        }
        int ts = cL - GRU_W; if (ts < 0) ts = 0;
        int te = cL + CH_L;
        float h0 = 0.f, h1 = 0.f;

        float4 buf[4];
#pragma unroll
        for (int i = 0; i < 4; i++) {
            int t = ts + i; if (t > TT - 1) t = TT - 1;
            buf[t & 3] = g_xT[(size_t)t * BB + b];
        }
#pragma unroll 4
        for (int t = ts; t < te; t++) {
            float4 xv = buf[t & 3];
            int tn = t + 4; if (tn > TT - 1) tn = TT - 1;
            buf[t & 3] = g_xT[(size_t)tn * BB + b];

            // input gates (off critical path)
            float gr0 = fmaf(wih[0][0], xv.x, fmaf(wih[0][1], xv.y, fmaf(wih[0][2], xv.z, bih[0])));
            float gr1 = fmaf(wih[1][0], xv.x, fmaf(wih[1][1], xv.y, fmaf(wih[1][2], xv.z, bih[1])));
            float gz0 = fmaf(wih[2][0], xv.x, fmaf(wih[2][1], xv.y, fmaf(wih[2][2], xv.z, bih[2])));
            float gz1 = fmaf(wih[3][0], xv.x, fmaf(wih[3][1], xv.y, fmaf(wih[3][2], xv.z, bih[3])));
            float gn0 = fmaf(wih[4][0], xv.x, fmaf(wih[4][1], xv.y, fmaf(wih[4][2], xv.z, bih[4])));
            float gn1 = fmaf(wih[5][0], xv.x, fmaf(wih[5][1], xv.y, fmaf(wih[5][2], xv.z, bih[5])));

            float hr0 = fmaf(whh[0][0], h0, fmaf(whh[0][1], h1, bhh[0]));
            float hr1 = fmaf(whh[1][0], h0, fmaf(whh[1][1], h1, bhh[1]));
            float hz0 = fmaf(whh[2][0], h0, fmaf(whh[2][1], h1, bhh[2]));
            float hz1 = fmaf(whh[3][0], h0, fmaf(whh[3][1], h1, bhh[3]));
            float hn0 = fmaf(whh[4][0], h0, fmaf(whh[4][1], h1, bhh[4]));
            float hn1 = fmaf(whh[5][0], h0, fmaf(whh[5][1], h1, bhh[5]));
            // sigmoid(x) = 0.5*tanh(0.5x)+0.5
            float r0 = fmaf(0.5f, tanh_apx(0.5f * (gr0 + hr0)), 0.5f);
            float r1 = fmaf(0.5f, tanh_apx(0.5f * (gr1 + hr1)), 0.5f);
            float z0 = fmaf(0.5f, tanh_apx(0.5f * (gz0 + hz0)), 0.5f);
            float z1 = fmaf(0.5f, tanh_apx(0.5f * (gz1 + hz1)), 0.5f);
            float n0 = tanh_apx(fmaf(r0, hn0, gn0));
            float n1 = tanh_apx(fmaf(r1, hn1, gn1));
            h0 = fmaf(z0, h0 - n0, n0);
            h1 = fmaf(z1, h1 - n1, n1);
            if (t >= cL) g_h[(size_t)t * BB + b] = make_float2(h0, h1);
        }
    } else {
        // normalized HMM params
        float lA00, lA01, lA10, lA11, lpi0, lpi1;
        {
            float a0 = log_A[0], a1 = log_A[1], a2 = log_A[2], a3 = log_A[3];
            float m0 = fmaxf(a0, a1);
            float s0 = m0 + logf(expf(a0 - m0) + expf(a1 - m0));
            float m1 = fmaxf(a2, a3);
            float s1 = m1 + logf(expf(a2 - m1) + expf(a3 - m1));
            lA00 = a0 - s0; lA01 = a1 - s0; lA10 = a2 - s1; lA11 = a3 - s1;
            float p0 = log_pi[0], p1 = log_pi[1];
            float mp = fmaxf(p0, p1);
            float sp = mp + logf(expf(p0 - mp) + expf(p1 - mp));
            lpi0 = p0 - sp; lpi1 = p1 - sp;
        }

        if (role == 1) {
            // ---------------- HMM forward chunk ----------------
            int ts = cL - HMM_W; if (ts < 0) ts = 0;
            int te = cL + CH_L;
            float a0, a1;
            int tstart;
            if (ts == 0) {
                float2 e0 = g_e[b];
                a0 = lpi0 + e0.x; a1 = lpi1 + e0.y;
                if (cL == 0) g_alpha[b] = make_float2(a0, a1);
                tstart = 1;
            } else {
                float2 ei = g_e[(size_t)ts * BB + b];
                a0 = ei.x; a1 = ei.y;   // arbitrary init; forgotten by mixing
                tstart = ts + 1;
            }
            float2 buf[4];
#pragma unroll
            for (int i = 0; i < 4; i++) {
                int t = tstart + i; if (t > TT - 1) t = TT - 1;
                buf[t & 3] = g_e[(size_t)t * BB + b];
            }
#pragma unroll 4
            for (int t = tstart; t < te; t++) {
                float2 ev = buf[t & 3];
                int tn = t + 4; if (tn > TT - 1) tn = TT - 1;
                buf[t & 3] = g_e[(size_t)tn * BB + b];
                float n0 = lse2(a0 + lA00, a1 + lA10) + ev.x;
                float n1 = lse2(a0 + lA01, a1 + lA11) + ev.y;
                a0 = n0; a1 = n1;
                if (t >= cL) g_alpha[(size_t)t * BB + b] = make_float2(a0, a1);
            }
        } else {
            // ---------------- HMM backward chunk ----------------
            int tend = cL + CH_L - 1;                  // last index this chunk owns
            int ti = tend + HMM_W; if (ti > TT - 1) ti = TT - 1;  // pseudo-start
            float b0v = 0.f, b1v = 0.f;
            if (ti == tend) g_beta[(size_t)ti * BB + b] = make_float2(0.f, 0.f);

            float2 buf[4];
#pragma unroll
            for (int i = 0; i < 4; i++) {
                int t = ti - 1 - i;                    // step t uses e[t+1]
                buf[t & 3] = g_e[(size_t)(t + 1) * BB + b];
            }
#pragma unroll 4
            for (int t = ti - 1; t >= cL; t--) {
                float2 ev = buf[t & 3];
                int ip = t - 3; if (ip < 0) ip = 0;
                buf[t & 3] = g_e[(size_t)ip * BB + b];
                float c0 = b0v + ev.x, c1 = b1v + ev.y;
                b0v = lse2(c0 + lA00, c1 + lA01);
                b1v = lse2(c0 + lA10, c1 + lA11);
                if (t <= tend) g_beta[(size_t)t * BB + b] = make_float2(b0v, b1v);
            }
        }
    }
}

// ============================================================
// Kernel C: tiled gate. Loads h/alpha/beta [T,B] tiles via smem
// transpose, reads Q / writes outputs coalesced along t.
// grid (B/32, T/32), 256 threads.
// ============================================================
__global__ void gate_kernel(const float* __restrict__ Q_seq, const float* __restrict__ Wg,
                            const float* __restrict__ by, float* __restrict__ out) {
    __shared__ float2 sa[32][33], sb[32][33], sh[32][33];
    int tid = threadIdx.x;
    int b0 = blockIdx.x << 5;
    int t0 = blockIdx.y << 5;

#pragma unroll
    for (int r = 0; r < 4; r++) {
        int t_l = (tid >> 5) + r * 8;
        int b_l = tid & 31;
        size_t o = (size_t)(t0 + t_l) * BB + (b0 + b_l);
        sa[t_l][b_l] = g_alpha[o];
        sb[t_l][b_l] = g_beta[o];
        sh[t_l][b_l] = g_h[o];
    }
    __syncthreads();

#pragma unroll
    for (int r = 0; r < 4; r++) {
        int b_l = (tid >> 5) + r * 8;
        int t_l = tid & 31;
        float2 av = sa[t_l][b_l];
        float2 bv = sb[t_l][b_l];
        float2 hv = sh[t_l][b_l];
        size_t id = (size_t)(b0 + b_l) * TT + (t0 + t_l);

        float lg0 = av.x + bv.x, lg1 = av.y + bv.y;
        float m = fmaxf(lg0, lg1);
        float ls = m + __logf(__expf(lg0 - m) + __expf(lg1 - m));
        lg0 -= ls; lg1 -= ls;
        float gam0 = __expf(lg0), gam1 = __expf(lg1);

        float wa[5], wb[5];
#pragma unroll
        for (int a = 0; a < 5; a++) {
            wa[a] = hv.x * Wg[a] + hv.y * Wg[5 + a];
            wb[a] = hv.x * Wg[10 + a] + hv.y * Wg[15 + a];
        }
        float ma = wa[0], mb = wb[0];
#pragma unroll
        for (int a = 1; a < 5; a++) {
            ma = fmaxf(ma, wa[a]);
            mb = fmaxf(mb, wb[a]);
        }
        float sa_ = 0.f, sb_ = 0.f;
#pragma unroll
        for (int a = 0; a < 5; a++) {
            wa[a] = __expf(wa[a] - ma); sa_ += wa[a];
            wb[a] = __expf(wb[a] - mb); sb_ += wb[a];
        }
        float ra = __fdividef(gam0, sa_), rb = __fdividef(gam1, sb_);

        const float* qp = Q_seq + id * 10;
        float V0 = gam0 * by[0] + gam1 * by[2];
        float V1 = gam0 * by[1] + gam1 * by[3];
        float g[5];
        float q[10];
#pragma unroll
        for (int a = 0; a < 10; a++) q[a] = __ldcs(qp + a);
#pragma unroll
        for (int a = 0; a < 5; a++) {
            float ga = wa[a] * ra + wb[a] * rb;
            g[a] = ga;
            V0 = fmaf(ga, q[a * 2 + 0], V0);
            V1 = fmaf(ga, q[a * 2 + 1], V1);
        }
        float mv = fmaxf(V0, V1);
        float lsv = mv + __logf(__expf(V0 - mv) + __expf(V1 - mv));

        float* out_pi = out + id * 2;
        __stcs(out_pi + 0, V0 - lsv);
        __stcs(out_pi + 1, V1 - lsv);
        float* out_g = out + (size_t)BB * TT * 2 + id * 5;
#pragma unroll
        for (int a = 0; a < 5; a++) __stcs(out_g + a, g[a]);
        float* out_lg = out + (size_t)BB * TT * 7 + id * 2;
        __stcs(out_lg + 0, lg0);
        __stcs(out_lg + 1, lg1);
    }
}

extern "C" void kernel_launch(void* const* d_in, const int* in_sizes, int n_in,
                              void* d_out, int out_size) {
    const float* x      = (const float*)d_in[0];
    const float* Q_seq  = (const float*)d_in[1];
    const float* log_pi = (const float*)d_in[2];
    const float* log_A  = (const float*)d_in[3];
    const float* fc1_w  = (const float*)d_in[4];
    const float* fc1_b  = (const float*)d_in[5];
    const float* fc2_w  = (const float*)d_in[6];
    const float* fc2_b  = (const float*)d_in[7];
    const float* w_ih   = (const float*)d_in[8];
    const float* w_hh   = (const float*)d_in[9];
    const float* b_ih   = (const float*)d_in[10];
    const float* b_hh   = (const float*)d_in[11];
    const float* Wg     = (const float*)d_in[12];
    const float* by     = (const float*)d_in[13];
    float* out = (float*)d_out;

    dim3 tiles(BB / 32, TT / 32);
    prep_kernel<<<tiles, 256>>>(x, fc1_w, fc1_b, fc2_w, fc2_b);
    scan_kernel<<<384, 128>>>(w_ih, b_ih, w_hh, b_hh, log_pi, log_A);
    gate_kernel<<<tiles, 256>>>(Q_seq, Wg, by, out);
}